// round 15
// baseline (speedup 1.0000x reference)
#include <cuda_runtime.h>
#include <cuda_fp16.h>
#include <cstdint>
#include <math.h>

#define Hh   16
#define Kh   64
#define Dd   1024
#define Mf   4096
#define Ss   2048
#define Bb   4
#define NTOK (Ss*Bb)      // 8192
#define BH   (Bb*Hh)      // 64
#define EPSL 1e-5f
#define LOG2E 1.44269504088896340736f
#define QSCALE (0.125f * LOG2E)

// ---------------- scratch buffers ----------------
__device__ __half g_x[(size_t)NTOK*Dd];
__device__ __half g_wqkv[(size_t)3*Dd*Dd];
__device__ __half g_wc[(size_t)Dd*Dd];
__device__ __half g_w1[(size_t)Mf*Dd];
__device__ __half g_w2[(size_t)Mf*Dd];
__device__ __half g_maskh[(size_t)Ss*Ss];          // pre-scaled by log2(e)
__device__ int    g_maskflag;
__device__ __half g_qkv[(size_t)NTOK*3*Dd];        // Q pre-scaled by 0.125*log2(e)
__device__ __half g_av[(size_t)NTOK*Dd];
__device__ float  g_attn[(size_t)NTOK*Dd];
__device__ float  g_u[(size_t)NTOK*Dd];
__device__ __half g_uh[(size_t)NTOK*Dd];
__device__ __half g_h1[(size_t)NTOK*Mf];
__device__ float  g_z[(size_t)NTOK*Dd];

// ---------------- helpers ----------------
__device__ __forceinline__ uint32_t smem_u32(const void* p){
    uint32_t a;
    asm("{ .reg .u64 t; cvta.to.shared.u64 t, %1; cvt.u32.u64 %0, t; }" : "=r"(a) : "l"(p));
    return a;
}
__device__ __forceinline__ uint32_t packf2(float lo, float hi){
    uint32_t r;
    asm("cvt.rn.f16x2.f32 %0, %1, %2;" : "=r"(r) : "f"(hi), "f"(lo));
    return r;
}
__device__ __forceinline__ uint32_t ex2h2(uint32_t x){
    uint32_t r;
    asm("ex2.approx.f16x2 %0, %1;" : "=r"(r) : "r"(x));
    return r;
}
__device__ __forceinline__ void cpasync16(uint32_t saddr, const void* gaddr){
    asm volatile("cp.async.cg.shared.global [%0], [%1], 16;" :: "r"(saddr), "l"(gaddr) : "memory");
}
__device__ __forceinline__ void ldmx4(uint32_t* r, uint32_t addr){
    asm volatile("ldmatrix.sync.aligned.m8n8.x4.shared.b16 {%0,%1,%2,%3}, [%4];"
                 : "=r"(r[0]), "=r"(r[1]), "=r"(r[2]), "=r"(r[3]) : "r"(addr));
}
__device__ __forceinline__ void ldmx4t(uint32_t* r, uint32_t addr){
    asm volatile("ldmatrix.sync.aligned.m8n8.x4.trans.shared.b16 {%0,%1,%2,%3}, [%4];"
                 : "=r"(r[0]), "=r"(r[1]), "=r"(r[2]), "=r"(r[3]) : "r"(addr));
}
__device__ __forceinline__ void mma16816(float* c, const uint32_t* a, const uint32_t* b){
    asm volatile("mma.sync.aligned.m16n8k16.row.col.f32.f16.f16.f32 "
                 "{%0,%1,%2,%3}, {%4,%5,%6,%7}, {%8,%9}, {%0,%1,%2,%3};"
                 : "+f"(c[0]), "+f"(c[1]), "+f"(c[2]), "+f"(c[3])
                 : "r"(a[0]), "r"(a[1]), "r"(a[2]), "r"(a[3]), "r"(b[0]), "r"(b[1]));
}

// ---------------- mma.sync fp16 NT GEMM, 128x64 tile, BK=64, 2-stage, 3 CTAs/SM ----------------
__global__ void __launch_bounds__(256,3) mma_gemm(
    const __half* __restrict__ A, const __half* __restrict__ B,
    float* __restrict__ Cf, __half* __restrict__ Ch,
    int Kd, long lda, long ldb, long ldc,
    float alpha, const float* __restrict__ add, long ldadd,
    const float* __restrict__ bias, int doRelu, int qkvMode)
{
    constexpr int BN   = 64;
    constexpr int BK   = 64;
    constexpr int LDS  = BK + 8;             // 72 halves
    constexpr int WN   = 32;
    constexpr int NT   = 4;
    constexpr int A_BYTES = 128 * LDS * 2;   // 18432
    constexpr int B_BYTES = BN  * LDS * 2;   // 9216
    constexpr int STAGE   = A_BYTES + B_BYTES;  // 27648

    extern __shared__ char smc[];
    const uint32_t sbase = smem_u32(smc);

    const int tid  = threadIdx.x;
    const int lane = tid & 31;
    const int wid  = tid >> 5;
    const int warpM = (wid & 3) * 32;
    const int warpN = (wid >> 2) * WN;

    const int  m0   = blockIdx.y * 128;
    const int  n0   = blockIdx.x * BN;
    const int  KT   = Kd / BK;

    const int la_row = tid >> 3, la_ch = tid & 7;
    auto load_stage = [&](int kt, int buf){
        const int k0 = kt * BK;
        const uint32_t s0 = sbase + buf * STAGE;
        #pragma unroll
        for (int it = 0; it < 4; it++){
            int row = la_row + it * 32;
            long g = (long)(m0 + row) * lda + k0 + la_ch * 8;
            cpasync16(s0 + (uint32_t)(row * (LDS*2) + la_ch*16), A + g);
        }
        #pragma unroll
        for (int it = 0; it < 2; it++){
            int row = la_row + it * 32;
            long g = (long)(n0 + row) * ldb + k0 + la_ch * 8;
            cpasync16(s0 + A_BYTES + (uint32_t)(row * (LDS*2) + la_ch*16), B + g);
        }
    };

    load_stage(0, 0);
    asm volatile("cp.async.commit_group;" ::: "memory");
    load_stage(1, 1);
    asm volatile("cp.async.commit_group;" ::: "memory");

    float acc[2][NT][4];
    #pragma unroll
    for (int i = 0; i < 2; i++)
        #pragma unroll
        for (int j = 0; j < NT; j++)
            #pragma unroll
            for (int e = 0; e < 4; e++) acc[i][j][e] = 0.0f;

    const int aRow = (lane & 15), aColHalf = (lane >> 4) * 8;
    const int bRow = (lane >> 4) * 8 + (lane & 7), bColHalf = ((lane >> 3) & 1) * 8;

    for (int kt = 0; kt < KT; kt++){
        asm volatile("cp.async.wait_group 1;" ::: "memory");
        __syncthreads();
        const int buf = kt & 1;
        const uint32_t sA0 = sbase + buf * STAGE;
        const uint32_t sB0 = sA0 + A_BYTES;

        #pragma unroll
        for (int ks = 0; ks < 4; ks++){
            const int k16 = ks * 16;
            uint32_t af[2][4];
            #pragma unroll
            for (int mt = 0; mt < 2; mt++){
                uint32_t addr = sA0 + (uint32_t)(((warpM + mt*16 + aRow) * LDS + k16 + aColHalf) * 2);
                ldmx4(af[mt], addr);
            }
            uint32_t b0[4], b1[4];
            ldmx4(b0, sB0 + (uint32_t)(((warpN + bRow) * LDS + k16 + bColHalf) * 2));
            ldmx4(b1, sB0 + (uint32_t)(((warpN + 16 + bRow) * LDS + k16 + bColHalf) * 2));
            #pragma unroll
            for (int mt = 0; mt < 2; mt++){
                mma16816(acc[mt][0], af[mt], b0+0);
                mma16816(acc[mt][1], af[mt], b0+2);
                mma16816(acc[mt][2], af[mt], b1+0);
                mma16816(acc[mt][3], af[mt], b1+2);
            }
        }
        __syncthreads();
        if (kt + 2 < KT) load_stage(kt + 2, buf);
        asm volatile("cp.async.commit_group;" ::: "memory");
    }

    #pragma unroll
    for (int mt = 0; mt < 2; mt++){
        #pragma unroll
        for (int j = 0; j < NT; j++){
            const int col = n0 + warpN + j*8 + (lane & 3) * 2;
            const float sc = qkvMode ? (((col % 3072) < 1024) ? QSCALE : 1.0f) : alpha;
            const float b0 = bias ? bias[col]   : 0.0f;
            const float b1 = bias ? bias[col+1] : 0.0f;
            #pragma unroll
            for (int half = 0; half < 2; half++){
                const long row = m0 + warpM + mt*16 + (lane >> 2) + half*8;
                float v0 = acc[mt][j][half*2+0] * sc + b0;
                float v1 = acc[mt][j][half*2+1] * sc + b1;
                if (add){
                    v0 += add[row * ldadd + col];
                    v1 += add[row * ldadd + col + 1];
                }
                if (doRelu){ v0 = fmaxf(v0, 0.0f); v1 = fmaxf(v1, 0.0f); }
                const long ci = row * ldc + col;
                if (Ch){
                    *(uint32_t*)(Ch + ci) = packf2(v0, v1);
                } else {
                    *(float2*)(Cf + ci) = make_float2(v0, v1);
                }
            }
        }
    }
}

// ---------------- fused flash attention (unchanged from R14) ----------------
#define FL_LQ 72
#define FL_QBYTES (128*FL_LQ*2)
#define FL_KB (64*FL_LQ*2)
#define FL_VB (64*FL_LQ*2)
#define FL_STAGE (FL_KB + FL_VB)
#define FL_SMQ   0
#define FL_SMST  FL_QBYTES
#define FL_SMEM  (FL_SMST + 3*FL_STAGE)      // 73728

__global__ void __launch_bounds__(256,2) flash_kernel(
    const __half* __restrict__ QKV,
    const __half* __restrict__ maskh,
    const int* __restrict__ maskFlag,
    __half* __restrict__ AV)
{
    extern __shared__ char smc[];
    const uint32_t sbase = smem_u32(smc);
    const int tid = threadIdx.x, lane = tid & 31, wid = tid >> 5;
    const int q0 = blockIdx.x * 128;
    const int z  = blockIdx.y;
    const long qOff = (long)(z >> 4) * 3072 + (long)(z & 15) * 64;
    const long kOff = qOff + 1024;
    const long vOff = qOff + 2048;
    const int hasMask = *maskFlag;

    auto load_q = [&](){
        #pragma unroll
        for (int it = 0; it < 4; it++){
            int idx = it*256 + tid;
            int row = idx >> 3, ch = idx & 7;
            long g = (long)(q0 + row) * 12288 + qOff + ch*8;
            uint32_t so = sbase + FL_SMQ + (uint32_t)(row*FL_LQ*2 + ch*16);
            cpasync16(so, QKV + g);
        }
    };
    auto load_stage = [&](int kt, int buf){
        const int t0 = kt * 64;
        const uint32_t s0 = sbase + FL_SMST + buf*FL_STAGE;
        #pragma unroll
        for (int it = 0; it < 2; it++){
            int idx = it*256 + tid;
            int row = idx >> 3, ch = idx & 7;
            long gk = (long)(t0 + row) * 12288 + kOff + ch*8;
            uint32_t so = s0 + (uint32_t)(row*FL_LQ*2 + ch*16);
            cpasync16(so, QKV + gk);
            long gv = (long)(t0 + row) * 12288 + vOff + ch*8;
            cpasync16(so + FL_KB, QKV + gv);
        }
    };

    load_q();
    load_stage(0, 0);
    asm volatile("cp.async.commit_group;" ::: "memory");
    load_stage(1, 1);
    asm volatile("cp.async.commit_group;" ::: "memory");
    asm volatile("cp.async.wait_group 1;" ::: "memory");
    __syncthreads();

    const int aRow = lane & 15, aCol = (lane >> 4) * 8;
    const int bRow = (lane >> 4) * 8 + (lane & 7), bCol = ((lane >> 3) & 1) * 8;

    uint32_t qf[4][4];
    #pragma unroll
    for (int kc = 0; kc < 4; kc++){
        uint32_t addr = sbase + FL_SMQ + (uint32_t)(((wid*16 + aRow)*FL_LQ + kc*16 + aCol) * 2);
        ldmx4(qf[kc], addr);
    }

    float O[8][4];
    #pragma unroll
    for (int j = 0; j < 8; j++){ O[j][0]=0; O[j][1]=0; O[j][2]=0; O[j][3]=0; }
    float lacc[4] = {0.0f, 0.0f, 0.0f, 0.0f};
    const uint32_t onesfrag[2] = {0x3C003C00u, 0x3C003C00u};
    float m0 = -INFINITY, m1 = -INFINITY;
    const int rloc = wid*16 + (lane >> 2);

    int buf = 0;
    for (int kt = 0; kt < 32; kt++){
        asm volatile("cp.async.wait_group 1;" ::: "memory");
        __syncthreads();
        const uint32_t sK = sbase + FL_SMST + buf*FL_STAGE;
        const uint32_t sV = sK + FL_KB;

        float S[8][4];
        #pragma unroll
        for (int j = 0; j < 8; j++){ S[j][0]=0; S[j][1]=0; S[j][2]=0; S[j][3]=0; }

        {
            uint32_t bcur[4], bnext[4];
            ldmx4(bcur, sK + (uint32_t)(((bRow) * FL_LQ + bCol) * 2));
            #pragma unroll
            for (int kc = 0; kc < 4; kc++){
                #pragma unroll
                for (int g = 0; g < 4; g++){
                    uint32_t* bk = ((kc*4 + g) & 1) ? bnext : bcur;
                    uint32_t* bl = ((kc*4 + g) & 1) ? bcur  : bnext;
                    int ng = g + 1, nkc = kc;
                    if (ng == 4){ ng = 0; nkc = kc + 1; }
                    if (nkc < 4)
                        ldmx4(bl, sK + (uint32_t)(((ng*16 + bRow)*FL_LQ + nkc*16 + bCol) * 2));
                    mma16816(S[2*g],   qf[kc], bk+0);
                    mma16816(S[2*g+1], qf[kc], bk+2);
                }
            }
        }

        const int t0 = kt * 64;
        float mx0 = -INFINITY, mx1 = -INFINITY;
        if (hasMask){
            const long mr0 = (long)(q0 + rloc) * 2048 + t0;
            const long mr1 = mr0 + 8 * 2048;
            #pragma unroll
            for (int j = 0; j < 8; j++){
                int c = j*8 + (lane & 3)*2;
                float2 k0v = __half22float2(*(const __half2*)(maskh + mr0 + c));
                float2 k1v = __half22float2(*(const __half2*)(maskh + mr1 + c));
                S[j][0] += k0v.x;
                S[j][1] += k0v.y;
                S[j][2] += k1v.x;
                S[j][3] += k1v.y;
                mx0 = fmaxf(mx0, fmaxf(S[j][0], S[j][1]));
                mx1 = fmaxf(mx1, fmaxf(S[j][2], S[j][3]));
            }
        } else {
            #pragma unroll
            for (int j = 0; j < 8; j++){
                mx0 = fmaxf(mx0, fmaxf(S[j][0], S[j][1]));
                mx1 = fmaxf(mx1, fmaxf(S[j][2], S[j][3]));
            }
        }
        mx0 = fmaxf(mx0, __shfl_xor_sync(0xFFFFFFFFu, mx0, 1));
        mx0 = fmaxf(mx0, __shfl_xor_sync(0xFFFFFFFFu, mx0, 2));
        mx1 = fmaxf(mx1, __shfl_xor_sync(0xFFFFFFFFu, mx1, 1));
        mx1 = fmaxf(mx1, __shfl_xor_sync(0xFFFFFFFFu, mx1, 2));
        float nm0 = fmaxf(m0, mx0), nm1 = fmaxf(m1, mx1);

        bool re = (nm0 != m0) || (nm1 != m1);
        if (__any_sync(0xFFFFFFFFu, re)){
            float f0 = (m0 > -INFINITY) ? exp2f(m0 - nm0) : 0.0f;
            float f1 = (m1 > -INFINITY) ? exp2f(m1 - nm1) : 0.0f;
            #pragma unroll
            for (int j = 0; j < 8; j++){
                O[j][0]*=f0; O[j][1]*=f0; O[j][2]*=f1; O[j][3]*=f1;
            }
            lacc[0]*=f0; lacc[1]*=f0; lacc[2]*=f1; lacc[3]*=f1;
        }
        m0 = nm0; m1 = nm1;

        {
            uint32_t vcur[4], vnext[4];
            ldmx4t(vcur, sV + (uint32_t)(((aRow)*FL_LQ + aCol) * 2));
            #pragma unroll
            for (int kc = 0; kc < 4; kc++){
                uint32_t ph[4];
                ph[0] = ex2h2(packf2(S[2*kc][0]   - m0, S[2*kc][1]   - m0));
                ph[1] = ex2h2(packf2(S[2*kc][2]   - m1, S[2*kc][3]   - m1));
                ph[2] = ex2h2(packf2(S[2*kc+1][0] - m0, S[2*kc+1][1] - m0));
                ph[3] = ex2h2(packf2(S[2*kc+1][2] - m1, S[2*kc+1][3] - m1));
                mma16816(lacc, ph, onesfrag);
                #pragma unroll
                for (int g = 0; g < 4; g++){
                    uint32_t* vf = ((kc*4 + g) & 1) ? vnext : vcur;
                    uint32_t* vl = ((kc*4 + g) & 1) ? vcur  : vnext;
                    int ng = g + 1, nkc = kc;
                    if (ng == 4){ ng = 0; nkc = kc + 1; }
                    if (nkc < 4)
                        ldmx4t(vl, sV + (uint32_t)(((nkc*16 + aRow)*FL_LQ + ng*16 + aCol) * 2));
                    mma16816(O[2*g],   ph, vf+0);
                    mma16816(O[2*g+1], ph, vf+2);
                }
            }
        }

        if (kt + 2 < 32){
            int nbuf = buf + 2; if (nbuf >= 3) nbuf -= 3;
            load_stage(kt + 2, nbuf);
        }
        asm volatile("cp.async.commit_group;" ::: "memory");
        if (++buf == 3) buf = 0;
    }

    const long hOff = (long)z * 64;
    const float inv0 = 1.0f / lacc[0], inv1 = 1.0f / lacc[2];
    #pragma unroll
    for (int j = 0; j < 8; j++){
        const int col = j*8 + (lane & 3)*2;
        const long a0 = (long)(q0 + rloc) * 4096 + hOff + col;
        const long a1 = a0 + 8L * 4096;
        *(uint32_t*)(AV + a0) = packf2(O[j][0]*inv0, O[j][1]*inv0);
        *(uint32_t*)(AV + a1) = packf2(O[j][2]*inv1, O[j][3]*inv1);
    }
}

// ---------------- fused fp32 -> fp16 conversion; seg7 = mask (scaled, sets flag) ----------------
struct CvtSegs {
    const float4* in[8];
    uint2*        out[8];
    long          start[9];
    int*          maskFlag;
};
__global__ void cvt_multi(CvtSegs s)
{
    long i = (long)blockIdx.x * 256 + threadIdx.x;
    if (i >= s.start[8]) return;
    int seg = 0;
    #pragma unroll
    for (int k = 1; k < 8; k++) if (i >= s.start[k]) seg = k;
    long j = i - s.start[seg];
    float4 v = s.in[seg][j];
    if (seg == 7){
        if (v.x != 0.0f || v.y != 0.0f || v.z != 0.0f || v.w != 0.0f)
            atomicOr(s.maskFlag, 1);
        v.x *= LOG2E; v.y *= LOG2E; v.z *= LOG2E; v.w *= LOG2E;
    }
    uint2 H;
    H.x = packf2(v.x, v.y);
    H.y = packf2(v.z, v.w);
    s.out[seg][j] = H;
}

// ---------------- layernorm over D=1024; optional fp16 output ----------------
__global__ void layernorm_kernel(const float* __restrict__ in,
                                 float* __restrict__ out,
                                 __half* __restrict__ oh,
                                 const float* __restrict__ gamma,
                                 const float* __restrict__ beta)
{
    const int row = blockIdx.x;
    const float* x = in + (size_t)row * Dd;
    const int tid = threadIdx.x;

    float v[4];
    float s = 0.0f, s2 = 0.0f;
    #pragma unroll
    for (int i = 0; i < 4; i++){
        v[i] = x[tid + i*256];
        s  += v[i];
        s2 += v[i]*v[i];
    }
    __shared__ float r1[256], r2[256];
    r1[tid] = s; r2[tid] = s2; __syncthreads();
    for (int off = 128; off > 0; off >>= 1){
        if (tid < off){ r1[tid] += r1[tid+off]; r2[tid] += r2[tid+off]; }
        __syncthreads();
    }
    float mean = r1[0] * (1.0f/Dd);
    float var  = r2[0] * (1.0f/Dd) - mean*mean;
    float inv  = rsqrtf(var + EPSL);
    #pragma unroll
    for (int i = 0; i < 4; i++){
        int c = tid + i*256;
        float y = (v[i] - mean) * inv * gamma[c] + beta[c];
        out[(size_t)row*Dd + c] = y;
        if (oh) oh[(size_t)row*Dd + c] = __float2half_rn(y);
    }
}

// ---------------- host side ----------------
static const int SMEM_GEMM = 2 * 27648;   // 55296

struct GemmArgs {
    const __half *A, *B;
    float* Cf; __half *Ch;
    int M, N, Kd; long lda, ldb, ldc;
    float alpha; const float* add; long ldadd; const float* bias; int relu; int qkvMode;
};

static inline void run_gemm(const GemmArgs& a){
    dim3 grid(a.N / 64, a.M / 128, 1);
    mma_gemm<<<grid, 256, SMEM_GEMM>>>(a.A, a.B, a.Cf, a.Ch,
                                       a.Kd, a.lda, a.ldb, a.ldc,
                                       a.alpha, a.add, a.ldadd, a.bias, a.relu, a.qkvMode);
}

extern "C" void kernel_launch(void* const* d_in, const int* in_sizes, int n_in,
                              void* d_out, int out_size)
{
    const float* x     = (const float*)d_in[0];
    const float* mask  = (const float*)d_in[1];
    const float* wq    = (const float*)d_in[2];
    const float* wk    = (const float*)d_in[3];
    const float* wv    = (const float*)d_in[4];
    const float* wc    = (const float*)d_in[5];
    const float* w1_w  = (const float*)d_in[6];
    const float* w1_b  = (const float*)d_in[7];
    const float* w2_w  = (const float*)d_in[8];
    const float* w2_b  = (const float*)d_in[9];
    const float* ln1_g = (const float*)d_in[10];
    const float* ln1_b = (const float*)d_in[11];
    const float* ln2_g = (const float*)d_in[12];
    const float* ln2_b = (const float*)d_in[13];
    float* out = (float*)d_out;

    cudaFuncSetAttribute((const void*)mma_gemm,     cudaFuncAttributeMaxDynamicSharedMemorySize, SMEM_GEMM);
    cudaFuncSetAttribute((const void*)flash_kernel, cudaFuncAttributeMaxDynamicSharedMemorySize, FL_SMEM);

    __half *xh,*pwqkv,*pwc,*pw1,*pw2,*pmask;
    __half *qkv,*av,*uh,*h1;
    float *attn,*u,*z;
    int* pflag;
    cudaGetSymbolAddress((void**)&xh,    g_x);
    cudaGetSymbolAddress((void**)&pwqkv, g_wqkv);
    cudaGetSymbolAddress((void**)&pwc,   g_wc);
    cudaGetSymbolAddress((void**)&pw1,   g_w1);
    cudaGetSymbolAddress((void**)&pw2,   g_w2);
    cudaGetSymbolAddress((void**)&pmask, g_maskh);
    cudaGetSymbolAddress((void**)&pflag, g_maskflag);
    cudaGetSymbolAddress((void**)&qkv,   g_qkv);
    cudaGetSymbolAddress((void**)&av,    g_av);
    cudaGetSymbolAddress((void**)&attn,  g_attn);
    cudaGetSymbolAddress((void**)&u,     g_u);
    cudaGetSymbolAddress((void**)&uh,    g_uh);
    cudaGetSymbolAddress((void**)&h1,    g_h1);
    cudaGetSymbolAddress((void**)&z,     g_z);

    cudaMemsetAsync(pflag, 0, sizeof(int));

    {
        CvtSegs s;
        const float* srcs[8] = {x, wq, wk, wv, wc, w1_w, w2_w, mask};
        __half*      dsts[8] = {xh, pwqkv, pwqkv + (size_t)Dd*Dd, pwqkv + (size_t)2*Dd*Dd,
                                pwc, pw1, pw2, pmask};
        long lens[8] = {(long)NTOK*Dd, (long)Dd*Dd, (long)Dd*Dd, (long)Dd*Dd,
                        (long)Dd*Dd, (long)Mf*Dd, (long)Mf*Dd, (long)Ss*Ss};
        long acc = 0;
        for (int i = 0; i < 8; i++){
            s.in[i]  = (const float4*)srcs[i];
            s.out[i] = (uint2*)dsts[i];
            s.start[i] = acc;
            acc += lens[i] / 4;
        }
        s.start[8] = acc;
        s.maskFlag = pflag;
        cvt_multi<<<(unsigned)((acc + 255) / 256), 256>>>(s);
    }

    GemmArgs a;
    // QKV = x @ wqkv^T
    a = {xh,pwqkv, nullptr,qkv, NTOK,3*Dd,Dd, Dd,Dd,3*Dd, 1.0f, nullptr,0, nullptr,0, 1};
    run_gemm(a);
    // fused attention
    {
        dim3 g(Ss/128, BH);
        flash_kernel<<<g, 256, FL_SMEM>>>(qkv, pmask, pflag, av);
    }
    // attn = av @ wc^T + x  (fp32)
    a = {av,pwc, attn,nullptr, NTOK,Dd,Dd, Dd,Dd,Dd, 1.0f, x,Dd, nullptr,0, 0};
    run_gemm(a);
    // u = LN1(attn)
    layernorm_kernel<<<NTOK, 256>>>(attn, u, uh, ln1_g, ln1_b);
    // h1 = relu(u @ w1^T + b1)
    a = {uh,pw1, nullptr,h1, NTOK,Mf,Dd, Dd,Dd,Mf, 1.0f, nullptr,0, w1_b,1, 0};
    run_gemm(a);
    // z = h1 @ w2^T + b2 + u  (fp32)
    a = {h1,pw2, z,nullptr, NTOK,Dd,Mf, Mf,Mf,Dd, 1.0f, u,Dd, w2_b,0, 0};
    run_gemm(a);
    // out = LN2(z)
    layernorm_kernel<<<NTOK, 256>>>(z, out, nullptr, ln2_g, ln2_b);
}

// round 16
// speedup vs baseline: 1.1262x; 1.1262x over previous
#include <cuda_runtime.h>
#include <cuda_fp16.h>
#include <cstdint>
#include <math.h>

#define Hh   16
#define Kh   64
#define Dd   1024
#define Mf   4096
#define Ss   2048
#define Bb   4
#define NTOK (Ss*Bb)      // 8192
#define BH   (Bb*Hh)      // 64
#define EPSL 1e-5f
#define LOG2E 1.44269504088896340736f
#define QSCALE (0.125f * LOG2E)

// ---------------- scratch buffers ----------------
__device__ __half g_x[(size_t)NTOK*Dd];
__device__ __half g_wqkv[(size_t)3*Dd*Dd];
__device__ __half g_wc[(size_t)Dd*Dd];
__device__ __half g_w1[(size_t)Mf*Dd];
__device__ __half g_w2[(size_t)Mf*Dd];
__device__ __half g_maskh[(size_t)Ss*Ss];          // pre-scaled by log2(e)
__device__ int    g_maskflag;
__device__ __half g_qkv[(size_t)NTOK*3*Dd];        // Q pre-scaled by 0.125*log2(e)
__device__ __half g_av[(size_t)NTOK*Dd];
__device__ float  g_attn[(size_t)NTOK*Dd];
__device__ float  g_u[(size_t)NTOK*Dd];
__device__ __half g_uh[(size_t)NTOK*Dd];
__device__ __half g_h1[(size_t)NTOK*Mf];
__device__ float  g_z[(size_t)NTOK*Dd];

// ---------------- helpers ----------------
__device__ __forceinline__ uint32_t smem_u32(const void* p){
    uint32_t a;
    asm("{ .reg .u64 t; cvta.to.shared.u64 t, %1; cvt.u32.u64 %0, t; }" : "=r"(a) : "l"(p));
    return a;
}
__device__ __forceinline__ uint32_t packf2(float lo, float hi){
    uint32_t r;
    asm("cvt.rn.f16x2.f32 %0, %1, %2;" : "=r"(r) : "f"(hi), "f"(lo));
    return r;
}
__device__ __forceinline__ uint32_t ex2h2(uint32_t x){
    uint32_t r;
    asm("ex2.approx.f16x2 %0, %1;" : "=r"(r) : "r"(x));
    return r;
}
__device__ __forceinline__ void cpasync16(uint32_t saddr, const void* gaddr){
    asm volatile("cp.async.cg.shared.global [%0], [%1], 16;" :: "r"(saddr), "l"(gaddr) : "memory");
}
__device__ __forceinline__ void ldmx4(uint32_t* r, uint32_t addr){
    asm volatile("ldmatrix.sync.aligned.m8n8.x4.shared.b16 {%0,%1,%2,%3}, [%4];"
                 : "=r"(r[0]), "=r"(r[1]), "=r"(r[2]), "=r"(r[3]) : "r"(addr));
}
__device__ __forceinline__ void ldmx4t(uint32_t* r, uint32_t addr){
    asm volatile("ldmatrix.sync.aligned.m8n8.x4.trans.shared.b16 {%0,%1,%2,%3}, [%4];"
                 : "=r"(r[0]), "=r"(r[1]), "=r"(r[2]), "=r"(r[3]) : "r"(addr));
}
__device__ __forceinline__ void mma16816(float* c, const uint32_t* a, const uint32_t* b){
    asm volatile("mma.sync.aligned.m16n8k16.row.col.f32.f16.f16.f32 "
                 "{%0,%1,%2,%3}, {%4,%5,%6,%7}, {%8,%9}, {%0,%1,%2,%3};"
                 : "+f"(c[0]), "+f"(c[1]), "+f"(c[2]), "+f"(c[3])
                 : "r"(a[0]), "r"(a[1]), "r"(a[2]), "r"(a[3]), "r"(b[0]), "r"(b[1]));
}

// ---------------- mma.sync fp16 NT GEMM, 128x128, BK=64, 3-stage (R14 proven) ----------------
__global__ void __launch_bounds__(256,2) mma_gemm(
    const __half* __restrict__ A, const __half* __restrict__ B,
    float* __restrict__ Cf, __half* __restrict__ Ch,
    int Kd, long lda, long ldb, long ldc,
    float alpha, const float* __restrict__ add, long ldadd,
    const float* __restrict__ bias, int doRelu, int qkvMode)
{
    constexpr int BN   = 128;
    constexpr int BK   = 64;
    constexpr int LDS  = BK + 8;
    constexpr int WN   = BN / 2;
    constexpr int NT   = WN / 8;
    constexpr int A_BYTES = 128 * LDS * 2;
    constexpr int B_BYTES = BN  * LDS * 2;
    constexpr int STAGE   = A_BYTES + B_BYTES;

    extern __shared__ char smc[];
    const uint32_t sbase = smem_u32(smc);

    const int tid  = threadIdx.x;
    const int lane = tid & 31;
    const int wid  = tid >> 5;
    const int warpM = (wid & 3) * 32;
    const int warpN = (wid >> 2) * WN;

    const int  m0   = blockIdx.y * 128;
    const int  n0   = blockIdx.x * BN;
    const int  KT   = Kd / BK;

    const int la_row = tid >> 3, la_ch = tid & 7;
    auto load_piece = [&](int kt, int buf, int piece){
        const int k0 = kt * BK;
        const uint32_t s0 = sbase + buf * STAGE;
        if (piece < 4){
            int row = la_row + piece * 32;
            long g = (long)(m0 + row) * lda + k0 + la_ch * 8;
            cpasync16(s0 + (uint32_t)(row * (LDS*2) + la_ch*16), A + g);
        } else {
            int row = la_row + (piece - 4) * 32;
            long g = (long)(n0 + row) * ldb + k0 + la_ch * 8;
            cpasync16(s0 + A_BYTES + (uint32_t)(row * (LDS*2) + la_ch*16), B + g);
        }
    };
    auto load_stage = [&](int kt, int buf){
        #pragma unroll
        for (int p = 0; p < 8; p++) load_piece(kt, buf, p);
    };

    load_stage(0, 0);
    asm volatile("cp.async.commit_group;" ::: "memory");
    load_stage(1, 1);
    asm volatile("cp.async.commit_group;" ::: "memory");

    float acc[2][NT][4];
    #pragma unroll
    for (int i = 0; i < 2; i++)
        #pragma unroll
        for (int j = 0; j < NT; j++)
            #pragma unroll
            for (int e = 0; e < 4; e++) acc[i][j][e] = 0.0f;

    const int aRow = (lane & 15), aColHalf = (lane >> 4) * 8;
    const int bRow = (lane >> 4) * 8 + (lane & 7), bColHalf = ((lane >> 3) & 1) * 8;

    int buf = 0;
    for (int kt = 0; kt < KT; kt++){
        asm volatile("cp.async.wait_group 1;" ::: "memory");
        __syncthreads();
        const uint32_t sA0 = sbase + buf * STAGE;
        const uint32_t sB0 = sA0 + A_BYTES;
        const bool pf = (kt + 2 < KT);
        int nbuf = buf + 2; if (nbuf >= 3) nbuf -= 3;

        #pragma unroll
        for (int ks = 0; ks < 4; ks++){
            const int k16 = ks * 16;
            uint32_t af[2][4];
            #pragma unroll
            for (int mt = 0; mt < 2; mt++){
                uint32_t addr = sA0 + (uint32_t)(((warpM + mt*16 + aRow) * LDS + k16 + aColHalf) * 2);
                ldmx4(af[mt], addr);
            }
            uint32_t bcur[4], bnext[4];
            ldmx4(bcur, sB0 + (uint32_t)(((warpN + bRow) * LDS + k16 + bColHalf) * 2));
            if (pf){
                load_piece(kt + 2, nbuf, ks*2);
                load_piece(kt + 2, nbuf, ks*2 + 1);
            }
            #pragma unroll
            for (int g = 0; g < NT/2; g++){
                uint32_t* bf = (g & 1) ? bnext : bcur;
                uint32_t* bl = (g & 1) ? bcur  : bnext;
                if (g + 1 < NT/2)
                    ldmx4(bl, sB0 + (uint32_t)(((warpN + (g+1)*16 + bRow) * LDS + k16 + bColHalf) * 2));
                #pragma unroll
                for (int mt = 0; mt < 2; mt++){
                    mma16816(acc[mt][2*g],   af[mt], bf+0);
                    mma16816(acc[mt][2*g+1], af[mt], bf+2);
                }
            }
        }
        asm volatile("cp.async.commit_group;" ::: "memory");
        if (++buf == 3) buf = 0;
    }

    #pragma unroll
    for (int mt = 0; mt < 2; mt++){
        #pragma unroll
        for (int j = 0; j < NT; j++){
            const int col = n0 + warpN + j*8 + (lane & 3) * 2;
            const float sc = qkvMode ? (((col % 3072) < 1024) ? QSCALE : 1.0f) : alpha;
            const float b0 = bias ? bias[col]   : 0.0f;
            const float b1 = bias ? bias[col+1] : 0.0f;
            #pragma unroll
            for (int half = 0; half < 2; half++){
                const long row = m0 + warpM + mt*16 + (lane >> 2) + half*8;
                float v0 = acc[mt][j][half*2+0] * sc + b0;
                float v1 = acc[mt][j][half*2+1] * sc + b1;
                if (add){
                    v0 += add[row * ldadd + col];
                    v1 += add[row * ldadd + col + 1];
                }
                if (doRelu){ v0 = fmaxf(v0, 0.0f); v1 = fmaxf(v1, 0.0f); }
                const long ci = row * ldc + col;
                if (Ch){
                    *(uint32_t*)(Ch + ci) = packf2(v0, v1);
                } else {
                    *(float2*)(Cf + ci) = make_float2(v0, v1);
                }
            }
        }
    }
}

// ---------------- fused flash attention (R14 proven) ----------------
#define FL_LQ 72
#define FL_QBYTES (128*FL_LQ*2)
#define FL_KB (64*FL_LQ*2)
#define FL_VB (64*FL_LQ*2)
#define FL_STAGE (FL_KB + FL_VB)
#define FL_SMQ   0
#define FL_SMST  FL_QBYTES
#define FL_SMEM  (FL_SMST + 3*FL_STAGE)      // 73728

__global__ void __launch_bounds__(256,2) flash_kernel(
    const __half* __restrict__ QKV,
    const __half* __restrict__ maskh,
    const int* __restrict__ maskFlag,
    __half* __restrict__ AV)
{
    extern __shared__ char smc[];
    const uint32_t sbase = smem_u32(smc);
    const int tid = threadIdx.x, lane = tid & 31, wid = tid >> 5;
    const int q0 = blockIdx.x * 128;
    const int z  = blockIdx.y;
    const long qOff = (long)(z >> 4) * 3072 + (long)(z & 15) * 64;
    const long kOff = qOff + 1024;
    const long vOff = qOff + 2048;
    const int hasMask = *maskFlag;

    auto load_q = [&](){
        #pragma unroll
        for (int it = 0; it < 4; it++){
            int idx = it*256 + tid;
            int row = idx >> 3, ch = idx & 7;
            long g = (long)(q0 + row) * 12288 + qOff + ch*8;
            uint32_t so = sbase + FL_SMQ + (uint32_t)(row*FL_LQ*2 + ch*16);
            cpasync16(so, QKV + g);
        }
    };
    auto load_stage = [&](int kt, int buf){
        const int t0 = kt * 64;
        const uint32_t s0 = sbase + FL_SMST + buf*FL_STAGE;
        #pragma unroll
        for (int it = 0; it < 2; it++){
            int idx = it*256 + tid;
            int row = idx >> 3, ch = idx & 7;
            long gk = (long)(t0 + row) * 12288 + kOff + ch*8;
            uint32_t so = s0 + (uint32_t)(row*FL_LQ*2 + ch*16);
            cpasync16(so, QKV + gk);
            long gv = (long)(t0 + row) * 12288 + vOff + ch*8;
            cpasync16(so + FL_KB, QKV + gv);
        }
    };

    load_q();
    load_stage(0, 0);
    asm volatile("cp.async.commit_group;" ::: "memory");
    load_stage(1, 1);
    asm volatile("cp.async.commit_group;" ::: "memory");
    asm volatile("cp.async.wait_group 1;" ::: "memory");
    __syncthreads();

    const int aRow = lane & 15, aCol = (lane >> 4) * 8;
    const int bRow = (lane >> 4) * 8 + (lane & 7), bCol = ((lane >> 3) & 1) * 8;

    uint32_t qf[4][4];
    #pragma unroll
    for (int kc = 0; kc < 4; kc++){
        uint32_t addr = sbase + FL_SMQ + (uint32_t)(((wid*16 + aRow)*FL_LQ + kc*16 + aCol) * 2);
        ldmx4(qf[kc], addr);
    }

    float O[8][4];
    #pragma unroll
    for (int j = 0; j < 8; j++){ O[j][0]=0; O[j][1]=0; O[j][2]=0; O[j][3]=0; }
    float lacc[4] = {0.0f, 0.0f, 0.0f, 0.0f};
    const uint32_t onesfrag[2] = {0x3C003C00u, 0x3C003C00u};
    float m0 = -INFINITY, m1 = -INFINITY;
    const int rloc = wid*16 + (lane >> 2);

    int buf = 0;
    for (int kt = 0; kt < 32; kt++){
        asm volatile("cp.async.wait_group 1;" ::: "memory");
        __syncthreads();
        const uint32_t sK = sbase + FL_SMST + buf*FL_STAGE;
        const uint32_t sV = sK + FL_KB;

        float S[8][4];
        #pragma unroll
        for (int j = 0; j < 8; j++){ S[j][0]=0; S[j][1]=0; S[j][2]=0; S[j][3]=0; }

        {
            uint32_t bcur[4], bnext[4];
            ldmx4(bcur, sK + (uint32_t)(((bRow) * FL_LQ + bCol) * 2));
            #pragma unroll
            for (int kc = 0; kc < 4; kc++){
                #pragma unroll
                for (int g = 0; g < 4; g++){
                    uint32_t* bk = ((kc*4 + g) & 1) ? bnext : bcur;
                    uint32_t* bl = ((kc*4 + g) & 1) ? bcur  : bnext;
                    int ng = g + 1, nkc = kc;
                    if (ng == 4){ ng = 0; nkc = kc + 1; }
                    if (nkc < 4)
                        ldmx4(bl, sK + (uint32_t)(((ng*16 + bRow)*FL_LQ + nkc*16 + bCol) * 2));
                    mma16816(S[2*g],   qf[kc], bk+0);
                    mma16816(S[2*g+1], qf[kc], bk+2);
                }
            }
        }

        const int t0 = kt * 64;
        float mx0 = -INFINITY, mx1 = -INFINITY;
        if (hasMask){
            const long mr0 = (long)(q0 + rloc) * 2048 + t0;
            const long mr1 = mr0 + 8 * 2048;
            #pragma unroll
            for (int j = 0; j < 8; j++){
                int c = j*8 + (lane & 3)*2;
                float2 k0v = __half22float2(*(const __half2*)(maskh + mr0 + c));
                float2 k1v = __half22float2(*(const __half2*)(maskh + mr1 + c));
                S[j][0] += k0v.x;
                S[j][1] += k0v.y;
                S[j][2] += k1v.x;
                S[j][3] += k1v.y;
                mx0 = fmaxf(mx0, fmaxf(S[j][0], S[j][1]));
                mx1 = fmaxf(mx1, fmaxf(S[j][2], S[j][3]));
            }
        } else {
            #pragma unroll
            for (int j = 0; j < 8; j++){
                mx0 = fmaxf(mx0, fmaxf(S[j][0], S[j][1]));
                mx1 = fmaxf(mx1, fmaxf(S[j][2], S[j][3]));
            }
        }
        mx0 = fmaxf(mx0, __shfl_xor_sync(0xFFFFFFFFu, mx0, 1));
        mx0 = fmaxf(mx0, __shfl_xor_sync(0xFFFFFFFFu, mx0, 2));
        mx1 = fmaxf(mx1, __shfl_xor_sync(0xFFFFFFFFu, mx1, 1));
        mx1 = fmaxf(mx1, __shfl_xor_sync(0xFFFFFFFFu, mx1, 2));
        float nm0 = fmaxf(m0, mx0), nm1 = fmaxf(m1, mx1);

        bool re = (nm0 != m0) || (nm1 != m1);
        if (__any_sync(0xFFFFFFFFu, re)){
            float f0 = (m0 > -INFINITY) ? exp2f(m0 - nm0) : 0.0f;
            float f1 = (m1 > -INFINITY) ? exp2f(m1 - nm1) : 0.0f;
            #pragma unroll
            for (int j = 0; j < 8; j++){
                O[j][0]*=f0; O[j][1]*=f0; O[j][2]*=f1; O[j][3]*=f1;
            }
            lacc[0]*=f0; lacc[1]*=f0; lacc[2]*=f1; lacc[3]*=f1;
        }
        m0 = nm0; m1 = nm1;

        {
            uint32_t vcur[4], vnext[4];
            ldmx4t(vcur, sV + (uint32_t)(((aRow)*FL_LQ + aCol) * 2));
            #pragma unroll
            for (int kc = 0; kc < 4; kc++){
                uint32_t ph[4];
                ph[0] = ex2h2(packf2(S[2*kc][0]   - m0, S[2*kc][1]   - m0));
                ph[1] = ex2h2(packf2(S[2*kc][2]   - m1, S[2*kc][3]   - m1));
                ph[2] = ex2h2(packf2(S[2*kc+1][0] - m0, S[2*kc+1][1] - m0));
                ph[3] = ex2h2(packf2(S[2*kc+1][2] - m1, S[2*kc+1][3] - m1));
                mma16816(lacc, ph, onesfrag);
                #pragma unroll
                for (int g = 0; g < 4; g++){
                    uint32_t* vf = ((kc*4 + g) & 1) ? vnext : vcur;
                    uint32_t* vl = ((kc*4 + g) & 1) ? vcur  : vnext;
                    int ng = g + 1, nkc = kc;
                    if (ng == 4){ ng = 0; nkc = kc + 1; }
                    if (nkc < 4)
                        ldmx4t(vl, sV + (uint32_t)(((nkc*16 + aRow)*FL_LQ + ng*16 + aCol) * 2));
                    mma16816(O[2*g],   ph, vf+0);
                    mma16816(O[2*g+1], ph, vf+2);
                }
            }
        }

        if (kt + 2 < 32){
            int nbuf = buf + 2; if (nbuf >= 3) nbuf -= 3;
            load_stage(kt + 2, nbuf);
        }
        asm volatile("cp.async.commit_group;" ::: "memory");
        if (++buf == 3) buf = 0;
    }

    const long hOff = (long)z * 64;
    const float inv0 = 1.0f / lacc[0], inv1 = 1.0f / lacc[2];
    #pragma unroll
    for (int j = 0; j < 8; j++){
        const int col = j*8 + (lane & 3)*2;
        const long a0 = (long)(q0 + rloc) * 4096 + hOff + col;
        const long a1 = a0 + 8L * 4096;
        *(uint32_t*)(AV + a0) = packf2(O[j][0]*inv0, O[j][1]*inv0);
        *(uint32_t*)(AV + a1) = packf2(O[j][2]*inv1, O[j][3]*inv1);
    }
}

// ---------------- fused fp32 -> fp16 conversion; seg7 = mask (scaled, sets flag) ----------------
struct CvtSegs {
    const float4* in[8];
    uint2*        out[8];
    long          start[9];
    int*          maskFlag;
};
__global__ void cvt_multi(CvtSegs s)
{
    long i = (long)blockIdx.x * 256 + threadIdx.x;
    if (i >= s.start[8]) return;
    int seg = 0;
    #pragma unroll
    for (int k = 1; k < 8; k++) if (i >= s.start[k]) seg = k;
    long j = i - s.start[seg];
    float4 v = s.in[seg][j];
    if (seg == 7){
        if (v.x != 0.0f || v.y != 0.0f || v.z != 0.0f || v.w != 0.0f)
            atomicOr(s.maskFlag, 1);
        v.x *= LOG2E; v.y *= LOG2E; v.z *= LOG2E; v.w *= LOG2E;
    }
    uint2 H;
    H.x = packf2(v.x, v.y);
    H.y = packf2(v.z, v.w);
    s.out[seg][j] = H;
}

// ---------------- layernorm over D=1024, vectorized: 1 float4/thread ----------------
__global__ void layernorm_kernel(const float* __restrict__ in,
                                 float* __restrict__ out,
                                 __half* __restrict__ oh,
                                 const float* __restrict__ gamma,
                                 const float* __restrict__ beta)
{
    const int row = blockIdx.x;
    const int tid = threadIdx.x;
    const int lane = tid & 31, wrp = tid >> 5;

    float4 v = *((const float4*)(in + (size_t)row * Dd) + tid);
    float s  = v.x + v.y + v.z + v.w;
    float s2 = v.x*v.x + v.y*v.y + v.z*v.z + v.w*v.w;
    #pragma unroll
    for (int off = 16; off > 0; off >>= 1){
        s  += __shfl_xor_sync(0xFFFFFFFFu, s,  off);
        s2 += __shfl_xor_sync(0xFFFFFFFFu, s2, off);
    }
    __shared__ float r1[8], r2[8];
    if (lane == 0){ r1[wrp] = s; r2[wrp] = s2; }
    __syncthreads();
    float t1 = r1[lane & 7], t2 = r2[lane & 7];
    #pragma unroll
    for (int off = 4; off > 0; off >>= 1){
        t1 += __shfl_xor_sync(0xFFFFFFFFu, t1, off);
        t2 += __shfl_xor_sync(0xFFFFFFFFu, t2, off);
    }
    float mean = t1 * (1.0f/Dd);
    float var  = t2 * (1.0f/Dd) - mean*mean;
    float inv  = rsqrtf(var + EPSL);

    float4 gv = *((const float4*)gamma + tid);
    float4 bv = *((const float4*)beta  + tid);
    float4 y;
    y.x = (v.x - mean) * inv * gv.x + bv.x;
    y.y = (v.y - mean) * inv * gv.y + bv.y;
    y.z = (v.z - mean) * inv * gv.z + bv.z;
    y.w = (v.w - mean) * inv * gv.w + bv.w;
    *((float4*)(out + (size_t)row * Dd) + tid) = y;
    if (oh){
        uint2 H;
        H.x = packf2(y.x, y.y);
        H.y = packf2(y.z, y.w);
        *((uint2*)(oh + (size_t)row * Dd) + tid) = H;
    }
}

// ---------------- host side ----------------
static const int SMEM_GEMM = 3 * 36864;   // 110592

struct GemmArgs {
    const __half *A, *B;
    float* Cf; __half *Ch;
    int M, N, Kd; long lda, ldb, ldc;
    float alpha; const float* add; long ldadd; const float* bias; int relu; int qkvMode;
};

static inline void run_gemm(const GemmArgs& a){
    dim3 grid(a.N / 128, a.M / 128, 1);
    mma_gemm<<<grid, 256, SMEM_GEMM>>>(a.A, a.B, a.Cf, a.Ch,
                                       a.Kd, a.lda, a.ldb, a.ldc,
                                       a.alpha, a.add, a.ldadd, a.bias, a.relu, a.qkvMode);
}

extern "C" void kernel_launch(void* const* d_in, const int* in_sizes, int n_in,
                              void* d_out, int out_size)
{
    const float* x     = (const float*)d_in[0];
    const float* mask  = (const float*)d_in[1];
    const float* wq    = (const float*)d_in[2];
    const float* wk    = (const float*)d_in[3];
    const float* wv    = (const float*)d_in[4];
    const float* wc    = (const float*)d_in[5];
    const float* w1_w  = (const float*)d_in[6];
    const float* w1_b  = (const float*)d_in[7];
    const float* w2_w  = (const float*)d_in[8];
    const float* w2_b  = (const float*)d_in[9];
    const float* ln1_g = (const float*)d_in[10];
    const float* ln1_b = (const float*)d_in[11];
    const float* ln2_g = (const float*)d_in[12];
    const float* ln2_b = (const float*)d_in[13];
    float* out = (float*)d_out;

    cudaFuncSetAttribute((const void*)mma_gemm,     cudaFuncAttributeMaxDynamicSharedMemorySize, SMEM_GEMM);
    cudaFuncSetAttribute((const void*)flash_kernel, cudaFuncAttributeMaxDynamicSharedMemorySize, FL_SMEM);

    __half *xh,*pwqkv,*pwc,*pw1,*pw2,*pmask;
    __half *qkv,*av,*uh,*h1;
    float *attn,*u,*z;
    int* pflag;
    cudaGetSymbolAddress((void**)&xh,    g_x);
    cudaGetSymbolAddress((void**)&pwqkv, g_wqkv);
    cudaGetSymbolAddress((void**)&pwc,   g_wc);
    cudaGetSymbolAddress((void**)&pw1,   g_w1);
    cudaGetSymbolAddress((void**)&pw2,   g_w2);
    cudaGetSymbolAddress((void**)&pmask, g_maskh);
    cudaGetSymbolAddress((void**)&pflag, g_maskflag);
    cudaGetSymbolAddress((void**)&qkv,   g_qkv);
    cudaGetSymbolAddress((void**)&av,    g_av);
    cudaGetSymbolAddress((void**)&attn,  g_attn);
    cudaGetSymbolAddress((void**)&u,     g_u);
    cudaGetSymbolAddress((void**)&uh,    g_uh);
    cudaGetSymbolAddress((void**)&h1,    g_h1);
    cudaGetSymbolAddress((void**)&z,     g_z);

    cudaMemsetAsync(pflag, 0, sizeof(int));

    {
        CvtSegs s;
        const float* srcs[8] = {x, wq, wk, wv, wc, w1_w, w2_w, mask};
        __half*      dsts[8] = {xh, pwqkv, pwqkv + (size_t)Dd*Dd, pwqkv + (size_t)2*Dd*Dd,
                                pwc, pw1, pw2, pmask};
        long lens[8] = {(long)NTOK*Dd, (long)Dd*Dd, (long)Dd*Dd, (long)Dd*Dd,
                        (long)Dd*Dd, (long)Mf*Dd, (long)Mf*Dd, (long)Ss*Ss};
        long acc = 0;
        for (int i = 0; i < 8; i++){
            s.in[i]  = (const float4*)srcs[i];
            s.out[i] = (uint2*)dsts[i];
            s.start[i] = acc;
            acc += lens[i] / 4;
        }
        s.start[8] = acc;
        s.maskFlag = pflag;
        cvt_multi<<<(unsigned)((acc + 255) / 256), 256>>>(s);
    }

    GemmArgs a;
    // QKV = x @ wqkv^T
    a = {xh,pwqkv, nullptr,qkv, NTOK,3*Dd,Dd, Dd,Dd,3*Dd, 1.0f, nullptr,0, nullptr,0, 1};
    run_gemm(a);
    // fused attention
    {
        dim3 g(Ss/128, BH);
        flash_kernel<<<g, 256, FL_SMEM>>>(qkv, pmask, pflag, av);
    }
    // attn = av @ wc^T + x  (fp32)
    a = {av,pwc, attn,nullptr, NTOK,Dd,Dd, Dd,Dd,Dd, 1.0f, x,Dd, nullptr,0, 0};
    run_gemm(a);
    // u = LN1(attn)
    layernorm_kernel<<<NTOK, 256>>>(attn, u, uh, ln1_g, ln1_b);
    // h1 = relu(u @ w1^T + b1)
    a = {uh,pw1, nullptr,h1, NTOK,Mf,Dd, Dd,Dd,Mf, 1.0f, nullptr,0, w1_b,1, 0};
    run_gemm(a);
    // z = h1 @ w2^T + b2 + u  (fp32)
    a = {h1,pw2, z,nullptr, NTOK,Dd,Mf, Mf,Mf,Dd, 1.0f, u,Dd, w2_b,0, 0};
    run_gemm(a);
    // out = LN2(z)
    layernorm_kernel<<<NTOK, 256>>>(z, out, nullptr, ln2_g, ln2_b);
}